// round 1
// baseline (speedup 1.0000x reference)
#include <cuda_runtime.h>
#include <stdint.h>

#define BATCH 128
#define NQ    2000
#define NC    3
#define QC    6000          // NQ*NC
#define TOPK  100
#define NP    20
#define CHUNK 24            // ceil(6000/256)
#define NT    256

// Output layout (float32, reference tuple order, flattened):
#define OFF_BOXES  0                      // [128,100,4]   51200
#define OFF_SCORES 51200                  // [128,100]     12800
#define OFF_LABELS 64000                  // [128,100]     12800
#define OFF_PTS    76800                  // [128,100,20,2] 512000
#define OFF_MASK   588800                 // [128,100]     12800
// total 601600

__global__ __launch_bounds__(NT, 1)
void maptr_post_kernel(const float* __restrict__ cls,
                       const float* __restrict__ bbox,
                       const float* __restrict__ pts,
                       float* __restrict__ out)
{
    __shared__ float              sh_log[QC];
    __shared__ unsigned long long sh_w[NT / 32];
    __shared__ unsigned long long sh_best;
    __shared__ unsigned int       sel_mono[TOPK];
    __shared__ int                sel_bi[TOPK];
    __shared__ int                sel_lab[TOPK];
    __shared__ unsigned char      sel_msk[TOPK];

    const int b = blockIdx.x;
    const int t = threadIdx.x;

    // ---- stage last-layer logits through shared (coalesced) ----
    const float* logit = cls + (size_t)(5 * BATCH + b) * QC;
    for (int i = t; i < QC; i += NT) sh_log[i] = logit[i];
    __syncthreads();

    // ---- per-thread chunk of monotone keys in registers ----
    const int base = t * CHUNK;
    unsigned int kv[CHUNK];
#pragma unroll
    for (int j = 0; j < CHUNK; j++) {
        unsigned int m = 0u;                       // 0 == invalid/taken sentinel
        int g = base + j;
        if (g < QC) {
            unsigned int u = __float_as_uint(sh_log[g]);
            m = (u & 0x80000000u) ? ~u : (u | 0x80000000u);
        }
        kv[j] = m;
    }

    unsigned int taken = 0u;
    unsigned long long cur = 0ull;
#pragma unroll
    for (int j = 0; j < CHUNK; j++) {
        if (kv[j] != 0u) {
            unsigned long long cand =
                ((unsigned long long)kv[j] << 32) |
                (unsigned int)(0xFFFFFFFFu - (unsigned int)(base + j));
            if (cand > cur) cur = cand;
        }
    }

    // ---- 100 sequential argmax rounds ----
    for (int m = 0; m < TOPK; m++) {
        unsigned long long w = cur;
#pragma unroll
        for (int s = 16; s; s >>= 1) {
            unsigned long long o = __shfl_xor_sync(0xFFFFFFFFu, w, s);
            if (o > w) w = o;
        }
        if ((t & 31) == 0) sh_w[t >> 5] = w;
        __syncthreads();
        if (t == 0) {
            unsigned long long bst = sh_w[0];
#pragma unroll
            for (int i = 1; i < NT / 32; i++)
                if (sh_w[i] > bst) bst = sh_w[i];
            sh_best = bst;
        }
        __syncthreads();
        const unsigned long long bst = sh_best;

        if (cur == bst && bst != 0ull) {
            // unique winner (index encoded in key)
            int g = (int)(0xFFFFFFFFu - (unsigned int)bst);
            taken |= (1u << (g - base));
            // record selection
            sel_mono[m] = (unsigned int)(bst >> 32);
            sel_bi[m]   = g / NC;
            sel_lab[m]  = g % NC;
            // recompute my local max
            unsigned long long c = 0ull;
#pragma unroll
            for (int j = 0; j < CHUNK; j++) {
                if (!((taken >> j) & 1u) && kv[j] != 0u) {
                    unsigned long long cand =
                        ((unsigned long long)kv[j] << 32) |
                        (unsigned int)(0xFFFFFFFFu - (unsigned int)(base + j));
                    if (cand > c) c = cand;
                }
            }
            cur = c;
        }
    }
    __syncthreads();

    // ---- phase 2: decode + write ----
    const float* bb = bbox + (size_t)(5 * BATCH + b) * NQ * 4;
    const float* pp = pts  + (size_t)(5 * BATCH + b) * NQ * NP * 2;

    if (t < TOPK) {
        unsigned int mono = sel_mono[t];
        unsigned int u = (mono & 0x80000000u) ? (mono ^ 0x80000000u) : ~mono;
        float f = __uint_as_float(u);
        float score = 1.0f / (1.0f + expf(-f));
        int   bi    = sel_bi[t];
        int   lab   = sel_lab[t];

        float4 bv = *(const float4*)(bb + (size_t)bi * 4);
        float x1 = (bv.x - 0.5f * bv.z) * 30.0f - 15.0f;
        float y1 = (bv.y - 0.5f * bv.w) * 60.0f - 30.0f;
        float x2 = (bv.x + 0.5f * bv.z) * 30.0f - 15.0f;
        float y2 = (bv.y + 0.5f * bv.w) * 60.0f - 30.0f;

        bool mk = (x1 >= -20.0f) && (y1 >= -35.0f) && (x2 >= -20.0f) && (y2 >= -35.0f) &&
                  (x1 <=  20.0f) && (y1 <=  35.0f) && (x2 <=  20.0f) && (y2 <=  35.0f);
        sel_msk[t] = (unsigned char)mk;

        float* ob = out + OFF_BOXES + (size_t)(b * TOPK + t) * 4;
        if (!mk) { x1 = y1 = x2 = y2 = 0.0f; }
        ob[0] = x1; ob[1] = y1; ob[2] = x2; ob[3] = y2;

        out[OFF_SCORES + b * TOPK + t] = mk ? score : 0.0f;
        out[OFF_LABELS + b * TOPK + t] = mk ? (float)lab : -1.0f;
        out[OFF_MASK   + b * TOPK + t] = mk ? 1.0f : 0.0f;
    }
    __syncthreads();

    float* op = out + OFF_PTS + (size_t)b * TOPK * NP * 2;
    for (int k = t; k < TOPK * NP * 2; k += NT) {
        int m = k / (NP * 2);
        int j = k - m * (NP * 2);
        float v = 0.0f;
        if (sel_msk[m]) {
            float raw = pp[(size_t)sel_bi[m] * (NP * 2) + j];
            v = (j & 1) ? (raw * 60.0f - 30.0f) : (raw * 30.0f - 15.0f);
        }
        op[k] = v;
    }
}

extern "C" void kernel_launch(void* const* d_in, const int* in_sizes, int n_in,
                              void* d_out, int out_size)
{
    // Identify inputs by element count (robust to metadata ordering).
    const float* cls = nullptr;
    const float* bb  = nullptr;
    const float* pt  = nullptr;
    for (int i = 0; i < n_in; i++) {
        if      (in_sizes[i] == 4608000)  cls = (const float*)d_in[i];
        else if (in_sizes[i] == 6144000)  bb  = (const float*)d_in[i];
        else if (in_sizes[i] == 61440000) pt  = (const float*)d_in[i];
    }
    // Positional fallback
    if (!cls && n_in > 0) cls = (const float*)d_in[0];
    if (!bb  && n_in > 1) bb  = (const float*)d_in[1];
    if (!pt  && n_in > 2) pt  = (const float*)d_in[2];

    maptr_post_kernel<<<BATCH, NT>>>(cls, bb, pt, (float*)d_out);
    (void)out_size;
}

// round 2
// speedup vs baseline: 4.0410x; 4.0410x over previous
#include <cuda_runtime.h>
#include <stdint.h>

#define BATCH 128
#define NQ    2000
#define NC    3
#define QC    6000
#define TOPK  100
#define NP    20
#define NT    256
#define NJ    24            // ceil(QC/NT); last j valid only for t < 112
#define TAIL  112           // QC - 23*NT
#define NBINS 4096
#define CAND_CAP 1024

// Output layout (float32, reference tuple order, flattened):
#define OFF_BOXES  0                      // [128,100,4]
#define OFF_SCORES 51200                  // [128,100]
#define OFF_LABELS 64000                  // [128,100]
#define OFF_PTS    76800                  // [128,100,20,2]
#define OFF_MASK   588800                 // [128,100]

__global__ __launch_bounds__(NT, 1)
void maptr_post_kernel(const float* __restrict__ cls,
                       const float* __restrict__ bbox,
                       const float* __restrict__ pts,
                       float* __restrict__ out)
{
    __shared__ unsigned int       hist[NBINS];        // 16 KB
    __shared__ unsigned long long cand[CAND_CAP];     // 8 KB
    __shared__ int                n_cand;
    __shared__ unsigned int       warp_tot[NT / 32];
    __shared__ int                sh_bcut;
    __shared__ int                sel_bi[TOPK];
    __shared__ unsigned char      sel_msk[TOPK];

    const int b = blockIdx.x;
    const int t = threadIdx.x;

    for (int i = t; i < NBINS; i += NT) hist[i] = 0u;
    if (t == 0) n_cand = 0;
    __syncthreads();

    // ---- pass 1: monotone keys in regs + shared histogram of top 12 bits ----
    const float* logit = cls + (size_t)(5 * BATCH + b) * QC;
    unsigned int key[NJ];
#pragma unroll
    for (int j = 0; j < NJ; j++) {
        unsigned int m = 0u;
        if (j < NJ - 1 || t < TAIL) {
            unsigned int u = __float_as_uint(logit[t + j * NT]);
            m = (u & 0x80000000u) ? ~u : (u | 0x80000000u);
            atomicAdd(&hist[m >> 20], 1u);
        }
        key[j] = m;
    }
    __syncthreads();

    // ---- suffix scan (descending bins) to find cutoff bin ----
    // segment t covers bins [NBINS-1-16t .. NBINS-16-16t] in descending order
    const int bin_hi = NBINS - 1 - 16 * t;
    unsigned int ssum = 0u;
#pragma unroll
    for (int k = 0; k < 16; k++) ssum += hist[bin_hi - k];

    // inclusive scan across threads (t ascending == bins descending)
    unsigned int inc = ssum;
#pragma unroll
    for (int off = 1; off < 32; off <<= 1) {
        unsigned int v = __shfl_up_sync(0xFFFFFFFFu, inc, off);
        if ((t & 31) >= off) inc += v;
    }
    const int wid = t >> 5, lane = t & 31;
    if (lane == 31) warp_tot[wid] = inc;
    __syncthreads();
    unsigned int woff = 0u;
    for (int i = 0; i < wid; i++) woff += warp_tot[i];
    const unsigned int excl = woff + inc - ssum;   // keys in bins strictly above my segment

    if (excl < TOPK && excl + ssum >= TOPK) {      // exactly one thread
        unsigned int acc = excl;
        int bc = bin_hi;
#pragma unroll
        for (int k = 0; k < 16; k++) {
            acc += hist[bin_hi - k];
            if (acc >= TOPK) { bc = bin_hi - k; break; }
        }
        sh_bcut = bc;
    }
    __syncthreads();
    const unsigned int keycut = ((unsigned int)sh_bcut) << 20;

    // ---- pass 2: collect candidates >= cutoff ----
#pragma unroll
    for (int j = 0; j < NJ; j++) {
        bool valid = (j < NJ - 1 || t < TAIL);
        if (valid && key[j] >= keycut && key[j] != 0u) {
            int p = atomicAdd(&n_cand, 1);
            if (p < CAND_CAP)
                cand[p] = ((unsigned long long)key[j] << 32) |
                          (unsigned int)(0xFFFFFFFFu - (unsigned int)(t + j * NT));
        }
    }
    __syncthreads();
    const int C = (n_cand < CAND_CAP) ? n_cand : CAND_CAP;

    // ---- exact rank among candidates; rank<TOPK decodes directly ----
    const float* bb = bbox + (size_t)(5 * BATCH + b) * NQ * 4;

    for (int i = t; i < C; i += NT) {
        const unsigned long long me = cand[i];
        int rank = 0;
        int jj = 0;
        for (; jj + 4 <= C; jj += 4) {
            rank += (cand[jj]     > me);
            rank += (cand[jj + 1] > me);
            rank += (cand[jj + 2] > me);
            rank += (cand[jj + 3] > me);
        }
        for (; jj < C; jj++) rank += (cand[jj] > me);

        if (rank < TOPK) {
            unsigned int mono = (unsigned int)(me >> 32);
            unsigned int u = (mono & 0x80000000u) ? (mono ^ 0x80000000u) : ~mono;
            float f = __uint_as_float(u);
            float score = 1.0f / (1.0f + expf(-f));
            int   g   = (int)(0xFFFFFFFFu - (unsigned int)me);
            int   bi  = g / NC;
            int   lab = g - bi * NC;

            float4 bv = *(const float4*)(bb + (size_t)bi * 4);
            float x1 = (bv.x - 0.5f * bv.z) * 30.0f - 15.0f;
            float y1 = (bv.y - 0.5f * bv.w) * 60.0f - 30.0f;
            float x2 = (bv.x + 0.5f * bv.z) * 30.0f - 15.0f;
            float y2 = (bv.y + 0.5f * bv.w) * 60.0f - 30.0f;

            bool mk = (x1 >= -20.0f) && (y1 >= -35.0f) && (x2 >= -20.0f) && (y2 >= -35.0f) &&
                      (x1 <=  20.0f) && (y1 <=  35.0f) && (x2 <=  20.0f) && (y2 <=  35.0f);
            sel_bi[rank]  = bi;
            sel_msk[rank] = (unsigned char)mk;

            if (!mk) { x1 = y1 = x2 = y2 = 0.0f; }
            float* ob = out + OFF_BOXES + (size_t)(b * TOPK + rank) * 4;
            ob[0] = x1; ob[1] = y1; ob[2] = x2; ob[3] = y2;

            out[OFF_SCORES + b * TOPK + rank] = mk ? score : 0.0f;
            out[OFF_LABELS + b * TOPK + rank] = mk ? (float)lab : -1.0f;
            out[OFF_MASK   + b * TOPK + rank] = mk ? 1.0f : 0.0f;
        }
    }
    __syncthreads();

    // ---- pts gather: 100 selections x 40 contiguous floats ----
    const float* pp = pts + (size_t)(5 * BATCH + b) * NQ * NP * 2;
    float* op = out + OFF_PTS + (size_t)b * TOPK * NP * 2;
    for (int k = t; k < TOPK * NP * 2; k += NT) {
        int m = k / (NP * 2);
        int j = k - m * (NP * 2);
        float v = 0.0f;
        if (sel_msk[m]) {
            float raw = pp[(size_t)sel_bi[m] * (NP * 2) + j];
            v = (j & 1) ? (raw * 60.0f - 30.0f) : (raw * 30.0f - 15.0f);
        }
        op[k] = v;
    }
}

extern "C" void kernel_launch(void* const* d_in, const int* in_sizes, int n_in,
                              void* d_out, int out_size)
{
    const float* cls = nullptr;
    const float* bb  = nullptr;
    const float* pt  = nullptr;
    for (int i = 0; i < n_in; i++) {
        if      (in_sizes[i] == 4608000)  cls = (const float*)d_in[i];
        else if (in_sizes[i] == 6144000)  bb  = (const float*)d_in[i];
        else if (in_sizes[i] == 61440000) pt  = (const float*)d_in[i];
    }
    if (!cls && n_in > 0) cls = (const float*)d_in[0];
    if (!bb  && n_in > 1) bb  = (const float*)d_in[1];
    if (!pt  && n_in > 2) pt  = (const float*)d_in[2];

    maptr_post_kernel<<<BATCH, NT>>>(cls, bb, pt, (float*)d_out);
    (void)out_size;
}

// round 3
// speedup vs baseline: 5.4548x; 1.3499x over previous
#include <cuda_runtime.h>
#include <stdint.h>

#define BATCH 128
#define NQ    2000
#define NC    3
#define QC    6000
#define NV4   1500          // QC/4
#define TOPK  100
#define NP    20
#define NT    512
#define NJ4   3             // ceil(NV4/NT)
#define NBINS 4096
#define BPT   8             // NBINS/NT bins per thread in scan
#define CAND_CAP 1024

// Output layout (float32, reference tuple order, flattened):
#define OFF_BOXES  0
#define OFF_SCORES 51200
#define OFF_LABELS 64000
#define OFF_PTS    76800
#define OFF_MASK   588800

__global__ __launch_bounds__(NT, 1)
void maptr_post_kernel(const float* __restrict__ cls,
                       const float* __restrict__ bbox,
                       const float* __restrict__ pts,
                       float* __restrict__ out)
{
    __shared__ unsigned int       hist[NBINS];        // 16 KB
    __shared__ unsigned long long cand[CAND_CAP];     // 8 KB
    __shared__ int                n_cand;
    __shared__ unsigned int       warp_tot[NT / 32];
    __shared__ int                sh_bcut;

    const int b = blockIdx.x;
    const int t = threadIdx.x;

    for (int i = t; i < NBINS; i += NT) hist[i] = 0u;
    if (t == 0) n_cand = 0;
    __syncthreads();

    // ---- pass 1: float4 loads -> monotone keys in regs + 12-bit histogram ----
    const float4* logit4 = (const float4*)(cls + (size_t)(5 * BATCH + b) * QC);
    unsigned int key[NJ4 * 4];
#pragma unroll
    for (int v = 0; v < NJ4; v++) {
        const int idx4 = t + v * NT;
        unsigned int m0 = 0u, m1 = 0u, m2 = 0u, m3 = 0u;
        if (idx4 < NV4) {
            float4 w = logit4[idx4];
            unsigned int u;
            u = __float_as_uint(w.x); m0 = (u & 0x80000000u) ? ~u : (u | 0x80000000u);
            u = __float_as_uint(w.y); m1 = (u & 0x80000000u) ? ~u : (u | 0x80000000u);
            u = __float_as_uint(w.z); m2 = (u & 0x80000000u) ? ~u : (u | 0x80000000u);
            u = __float_as_uint(w.w); m3 = (u & 0x80000000u) ? ~u : (u | 0x80000000u);
            atomicAdd(&hist[m0 >> 20], 1u);
            atomicAdd(&hist[m1 >> 20], 1u);
            atomicAdd(&hist[m2 >> 20], 1u);
            atomicAdd(&hist[m3 >> 20], 1u);
        }
        key[v * 4 + 0] = m0; key[v * 4 + 1] = m1;
        key[v * 4 + 2] = m2; key[v * 4 + 3] = m3;
    }
    __syncthreads();

    // ---- suffix scan (descending bins) to find cutoff bin ----
    const int bin_hi = NBINS - 1 - BPT * t;
    unsigned int ssum = 0u;
#pragma unroll
    for (int k = 0; k < BPT; k++) ssum += hist[bin_hi - k];

    unsigned int inc = ssum;
#pragma unroll
    for (int off = 1; off < 32; off <<= 1) {
        unsigned int v = __shfl_up_sync(0xFFFFFFFFu, inc, off);
        if ((t & 31) >= off) inc += v;
    }
    const int wid = t >> 5, lane = t & 31;
    if (lane == 31) warp_tot[wid] = inc;
    __syncthreads();
    unsigned int woff = 0u;
    for (int i = 0; i < wid; i++) woff += warp_tot[i];
    const unsigned int excl = woff + inc - ssum;

    if (excl < TOPK && excl + ssum >= TOPK) {      // exactly one thread
        unsigned int acc = excl;
        int bc = bin_hi;
#pragma unroll
        for (int k = 0; k < BPT; k++) {
            acc += hist[bin_hi - k];
            if (acc >= TOPK) { bc = bin_hi - k; break; }
        }
        sh_bcut = bc;
    }
    __syncthreads();
    const unsigned int keycut = ((unsigned int)sh_bcut) << 20;

    // ---- pass 2: collect candidates >= cutoff ----
#pragma unroll
    for (int v = 0; v < NJ4; v++) {
        const int idx4 = t + v * NT;
        if (idx4 < NV4) {
#pragma unroll
            for (int c = 0; c < 4; c++) {
                unsigned int k = key[v * 4 + c];
                if (k >= keycut && k != 0u) {
                    int p = atomicAdd(&n_cand, 1);
                    if (p < CAND_CAP)
                        cand[p] = ((unsigned long long)k << 32) |
                                  (unsigned int)(0xFFFFFFFFu - (unsigned int)(idx4 * 4 + c));
                }
            }
        }
    }
    __syncthreads();
    const int C = (n_cand < CAND_CAP) ? n_cand : CAND_CAP;

    // ---- exact rank among candidates; rank<TOPK decodes + gathers directly ----
    const float* bbp = bbox + (size_t)(5 * BATCH + b) * NQ * 4;
    const float4* pp4 = (const float4*)(pts + (size_t)(5 * BATCH + b) * NQ * NP * 2);
    float4* op4 = (float4*)(out + OFF_PTS + (size_t)b * TOPK * NP * 2);

    for (int i = t; i < C; i += NT) {
        const unsigned long long me = cand[i];
        int rank = 0;
        int jj = 0;
        for (; jj + 4 <= C; jj += 4) {
            rank += (cand[jj]     > me);
            rank += (cand[jj + 1] > me);
            rank += (cand[jj + 2] > me);
            rank += (cand[jj + 3] > me);
        }
        for (; jj < C; jj++) rank += (cand[jj] > me);

        if (rank < TOPK) {
            unsigned int mono = (unsigned int)(me >> 32);
            unsigned int u = (mono & 0x80000000u) ? (mono ^ 0x80000000u) : ~mono;
            float f = __uint_as_float(u);
            float score = 1.0f / (1.0f + expf(-f));
            int   g   = (int)(0xFFFFFFFFu - (unsigned int)me);
            int   bi  = g / NC;
            int   lab = g - bi * NC;

            float4 bv = *(const float4*)(bbp + (size_t)bi * 4);
            float x1 = (bv.x - 0.5f * bv.z) * 30.0f - 15.0f;
            float y1 = (bv.y - 0.5f * bv.w) * 60.0f - 30.0f;
            float x2 = (bv.x + 0.5f * bv.z) * 30.0f - 15.0f;
            float y2 = (bv.y + 0.5f * bv.w) * 60.0f - 30.0f;

            bool mk = (x1 >= -20.0f) && (y1 >= -35.0f) && (x2 >= -20.0f) && (y2 >= -35.0f) &&
                      (x1 <=  20.0f) && (y1 <=  35.0f) && (x2 <=  20.0f) && (y2 <=  35.0f);

            if (!mk) { x1 = y1 = x2 = y2 = 0.0f; }
            float* ob = out + OFF_BOXES + (size_t)(b * TOPK + rank) * 4;
            ob[0] = x1; ob[1] = y1; ob[2] = x2; ob[3] = y2;
            out[OFF_SCORES + b * TOPK + rank] = mk ? score : 0.0f;
            out[OFF_LABELS + b * TOPK + rank] = mk ? (float)lab : -1.0f;
            out[OFF_MASK   + b * TOPK + rank] = mk ? 1.0f : 0.0f;

            // fused pts gather: 40 floats = 10 float4 per selection
            const float4* src = pp4 + (size_t)bi * (NP * 2 / 4);
            float4*       dst = op4 + (size_t)rank * (NP * 2 / 4);
            if (mk) {
#pragma unroll
                for (int q = 0; q < NP * 2 / 4; q++) {
                    float4 r = src[q];
                    r.x = r.x * 30.0f - 15.0f;
                    r.y = r.y * 60.0f - 30.0f;
                    r.z = r.z * 30.0f - 15.0f;
                    r.w = r.w * 60.0f - 30.0f;
                    dst[q] = r;
                }
            } else {
                float4 z = make_float4(0.0f, 0.0f, 0.0f, 0.0f);
#pragma unroll
                for (int q = 0; q < NP * 2 / 4; q++) dst[q] = z;
            }
        }
    }
}

extern "C" void kernel_launch(void* const* d_in, const int* in_sizes, int n_in,
                              void* d_out, int out_size)
{
    const float* cls = nullptr;
    const float* bb  = nullptr;
    const float* pt  = nullptr;
    for (int i = 0; i < n_in; i++) {
        if      (in_sizes[i] == 4608000)  cls = (const float*)d_in[i];
        else if (in_sizes[i] == 6144000)  bb  = (const float*)d_in[i];
        else if (in_sizes[i] == 61440000) pt  = (const float*)d_in[i];
    }
    if (!cls && n_in > 0) cls = (const float*)d_in[0];
    if (!bb  && n_in > 1) bb  = (const float*)d_in[1];
    if (!pt  && n_in > 2) pt  = (const float*)d_in[2];

    maptr_post_kernel<<<BATCH, NT>>>(cls, bb, pt, (float*)d_out);
    (void)out_size;
}